// round 1
// baseline (speedup 1.0000x reference)
#include <cuda_runtime.h>
#include <math.h>

#define BATCH 4
#define S_LEN 2048
#define D_DIM 1024
#define NH    16
#define DH    64
#define M_TOT (BATCH*S_LEN)

// Scratch (device globals: allocation-free per harness rules)
__device__ float  g_Q[BATCH*NH*S_LEN*DH];   // 32 MB, [B,H,S,dh]
__device__ float  g_K[BATCH*NH*S_LEN*DH];
__device__ float  g_V[BATCH*NH*S_LEN*DH];
__device__ float  g_H[M_TOT*D_DIM];         // attention heads output [B,S,D]
__device__ float2 g_tab[S_LEN*(D_DIM/2)];   // RoPE (cos,sin) table

// ---------------- RoPE table: inv_freq in double, angle rounded to fp32 ----------------
__global__ void rope_table_kernel() {
    int idx = blockIdx.x*blockDim.x + threadIdx.x;
    if (idx >= S_LEN*(D_DIM/2)) return;
    int s = idx >> 9;          // D_DIM/2 == 512
    int p = idx & 511;
    double inv = exp(-((double)(2*p) / (double)D_DIM) * log(10000.0));
    float ang = (float)s * (float)inv;
    float sn, cs;
    sincosf(ang, &sn, &cs);
    g_tab[idx] = make_float2(cs, sn);
}

// ---------------- SGEMM: out = A[M,K] @ W[N,K]^T + bias ----------------
// MODE 0: plain row-major [M,N] output
// MODE 1: scatter to [B,H,S,dh]
// MODE 2: RoPE epilogue + scatter to [B,H,S,dh]
template<int MODE>
__global__ __launch_bounds__(256) void gemm128(
    const float* __restrict__ A, const float* __restrict__ W,
    const float* __restrict__ bias, float* __restrict__ out)
{
    __shared__ float As[16][128];
    __shared__ float Bs[16][128];
    const int K = D_DIM, N = D_DIM;
    int tid = threadIdx.x;
    int tx = tid & 15, ty = tid >> 4;
    int m0 = blockIdx.y * 128, n0 = blockIdx.x * 128;

    float acc[8][8];
    #pragma unroll
    for (int i=0;i<8;i++)
        #pragma unroll
        for (int j=0;j<8;j++) acc[i][j] = 0.f;

    for (int k0 = 0; k0 < K; k0 += 16) {
        #pragma unroll
        for (int l=0;l<2;l++){
            int idx = tid + l*256;
            int r = idx >> 2;
            int c = (idx & 3) << 2;
            float4 va = *(const float4*)(A + (size_t)(m0+r)*K + k0 + c);
            As[c+0][r]=va.x; As[c+1][r]=va.y; As[c+2][r]=va.z; As[c+3][r]=va.w;
            float4 vb = *(const float4*)(W + (size_t)(n0+r)*K + k0 + c);
            Bs[c+0][r]=vb.x; Bs[c+1][r]=vb.y; Bs[c+2][r]=vb.z; Bs[c+3][r]=vb.w;
        }
        __syncthreads();
        #pragma unroll
        for (int kk=0;kk<16;kk++){
            float a[8], b[8];
            *(float4*)&a[0] = *(const float4*)&As[kk][ty*4];
            *(float4*)&a[4] = *(const float4*)&As[kk][64+ty*4];
            *(float4*)&b[0] = *(const float4*)&Bs[kk][tx*4];
            *(float4*)&b[4] = *(const float4*)&Bs[kk][64+tx*4];
            #pragma unroll
            for (int i=0;i<8;i++)
                #pragma unroll
                for (int j=0;j<8;j++)
                    acc[i][j] = fmaf(a[i], b[j], acc[i][j]);
        }
        __syncthreads();
    }

    #pragma unroll
    for (int gi=0; gi<2; gi++)
    #pragma unroll
    for (int i=0;i<4;i++){
        int m  = m0 + gi*64 + ty*4 + i;
        int bb = m >> 11;            // / S_LEN
        int s  = m & (S_LEN-1);
        #pragma unroll
        for (int gj=0; gj<2; gj++){
            int nb = n0 + gj*64 + tx*4;     // 4-aligned: two RoPE pairs
            float v0 = acc[gi*4+i][gj*4+0] + bias[nb+0];
            float v1 = acc[gi*4+i][gj*4+1] + bias[nb+1];
            float v2 = acc[gi*4+i][gj*4+2] + bias[nb+2];
            float v3 = acc[gi*4+i][gj*4+3] + bias[nb+3];
            if (MODE == 2) {
                float2 cs0 = g_tab[s*512 + (nb>>1)];
                float2 cs1 = g_tab[s*512 + (nb>>1) + 1];
                float e0 = v0*cs0.x - v1*cs0.y;
                float d0 = v0*cs0.y + v1*cs0.x;
                float e1 = v2*cs1.x - v3*cs1.y;
                float d1 = v2*cs1.y + v3*cs1.x;
                v0=e0; v1=d0; v2=e1; v3=d1;
            }
            float4 w = make_float4(v0,v1,v2,v3);
            if (MODE == 0) {
                *(float4*)(out + (size_t)m*N + nb) = w;
            } else {
                int h = nb >> 6, d = nb & 63;
                *(float4*)(out + ((size_t)(bb*NH + h)*S_LEN + s)*DH + d) = w;
            }
        }
    }
}

// ---------------- Flash attention: one (b,h,64-q-rows) per block ----------------
// smem: Qs[64][65] + KP[64][65] (K tile, reused for P) + Vs[64][65] = 49920 B (dynamic)
__global__ __launch_bounds__(256) void attn_kernel(
    const float* __restrict__ Q, const float* __restrict__ K,
    const float* __restrict__ V, float* __restrict__ O)
{
    extern __shared__ float sm[];
    float* Qs = sm;               // [64][65]
    float* KP = sm + 64*65;       // [64][65]
    float* Vs = sm + 2*64*65;     // [64][65]

    int tid = threadIdx.x;
    int tx = tid & 15, ty = tid >> 4;
    int qb = blockIdx.x, h = blockIdx.y, b = blockIdx.z;

    const float* Qp = Q + ((size_t)(b*NH + h)*S_LEN + qb*64)*DH;
    const float* Kp = K + (size_t)(b*NH + h)*S_LEN*DH;
    const float* Vp = V + (size_t)(b*NH + h)*S_LEN*DH;

    #pragma unroll
    for (int l=0;l<4;l++){
        int idx = tid + l*256;
        int r = idx >> 4;
        int c = (idx & 15) << 2;
        float4 qv = *(const float4*)(Qp + (size_t)r*DH + c);
        Qs[r*65+c+0]=qv.x; Qs[r*65+c+1]=qv.y; Qs[r*65+c+2]=qv.z; Qs[r*65+c+3]=qv.w;
    }

    float m_[4], l_[4], o_[4][4];
    #pragma unroll
    for (int i=0;i<4;i++){
        m_[i] = -1e30f; l_[i] = 0.f;
        #pragma unroll
        for (int j=0;j<4;j++) o_[i][j] = 0.f;
    }

    for (int t=0; t<S_LEN/64; t++){
        __syncthreads();   // previous PV reads (and Q load) complete before overwrite
        #pragma unroll
        for (int l=0;l<4;l++){
            int idx = tid + l*256;
            int r = idx >> 4;
            int c = (idx & 15) << 2;
            float4 kv = *(const float4*)(Kp + (size_t)(t*64+r)*DH + c);
            KP[r*65+c+0]=kv.x; KP[r*65+c+1]=kv.y; KP[r*65+c+2]=kv.z; KP[r*65+c+3]=kv.w;
            float4 vv = *(const float4*)(Vp + (size_t)(t*64+r)*DH + c);
            Vs[r*65+c+0]=vv.x; Vs[r*65+c+1]=vv.y; Vs[r*65+c+2]=vv.z; Vs[r*65+c+3]=vv.w;
        }
        __syncthreads();

        // S = Q K^T (64x64 tile), thread owns rows ty*4+i, cols tx*4+j
        float s4[4][4];
        #pragma unroll
        for (int i=0;i<4;i++)
            #pragma unroll
            for (int j=0;j<4;j++) s4[i][j] = 0.f;

        #pragma unroll 8
        for (int kk=0; kk<64; kk++){
            float a[4], kvv[4];
            #pragma unroll
            for (int i=0;i<4;i++) a[i]   = Qs[(ty*4+i)*65 + kk];
            #pragma unroll
            for (int j=0;j<4;j++) kvv[j] = KP[(tx*4+j)*65 + kk];
            #pragma unroll
            for (int i=0;i<4;i++)
                #pragma unroll
                for (int j=0;j<4;j++)
                    s4[i][j] = fmaf(a[i], kvv[j], s4[i][j]);
        }
        #pragma unroll
        for (int i=0;i<4;i++)
            #pragma unroll
            for (int j=0;j<4;j++) s4[i][j] *= 0.125f;   // 1/sqrt(64)

        // Online softmax update (per q-row, reduced across the 16 tx lanes)
        #pragma unroll
        for (int i=0;i<4;i++){
            float rm = s4[i][0];
            #pragma unroll
            for (int j=1;j<4;j++) rm = fmaxf(rm, s4[i][j]);
            #pragma unroll
            for (int off=8; off>0; off>>=1)
                rm = fmaxf(rm, __shfl_xor_sync(0xffffffffu, rm, off));
            float mn = fmaxf(m_[i], rm);
            float sum = 0.f;
            #pragma unroll
            for (int j=0;j<4;j++){
                s4[i][j] = __expf(s4[i][j] - mn);
                sum += s4[i][j];
            }
            #pragma unroll
            for (int off=8; off>0; off>>=1)
                sum += __shfl_xor_sync(0xffffffffu, sum, off);
            float alpha = __expf(m_[i] - mn);
            l_[i] = l_[i]*alpha + sum;
            m_[i] = mn;
            #pragma unroll
            for (int j=0;j<4;j++) o_[i][j] *= alpha;
        }

        __syncthreads();   // all K reads done before P overwrites KP
        #pragma unroll
        for (int i=0;i<4;i++)
            #pragma unroll
            for (int j=0;j<4;j++)
                KP[(ty*4+i)*65 + tx*4 + j] = s4[i][j];
        __syncthreads();

        // O += P @ V, thread owns rows ty*4+i, dh-cols tx*4+j
        #pragma unroll 8
        for (int kk=0; kk<64; kk++){
            float pa[4], vb[4];
            #pragma unroll
            for (int i=0;i<4;i++) pa[i] = KP[(ty*4+i)*65 + kk];
            #pragma unroll
            for (int j=0;j<4;j++) vb[j] = Vs[kk*65 + tx*4 + j];
            #pragma unroll
            for (int i=0;i<4;i++)
                #pragma unroll
                for (int j=0;j<4;j++)
                    o_[i][j] = fmaf(pa[i], vb[j], o_[i][j]);
        }
    }

    // Write heads to [B,S,D] layout (row = b*S+s, col = h*64+d)
    #pragma unroll
    for (int i=0;i<4;i++){
        float inv = 1.f / l_[i];
        int sg = qb*64 + ty*4 + i;
        float* op = O + ((size_t)b*S_LEN + sg)*D_DIM + h*DH + tx*4;
        #pragma unroll
        for (int j=0;j<4;j++) op[j] = o_[i][j]*inv;
    }
}

extern "C" void kernel_launch(void* const* d_in, const int* in_sizes, int n_in,
                              void* d_out, int out_size)
{
    const float* X  = (const float*)d_in[0];
    const float* Wq = (const float*)d_in[1];
    const float* bq = (const float*)d_in[2];
    const float* Wk = (const float*)d_in[3];
    const float* bk = (const float*)d_in[4];
    const float* Wv = (const float*)d_in[5];
    const float* bv = (const float*)d_in[6];
    const float* Wo = (const float*)d_in[7];
    const float* bo = (const float*)d_in[8];
    float* out = (float*)d_out;

    float *gq, *gk, *gv, *gh;
    cudaGetSymbolAddress((void**)&gq, g_Q);
    cudaGetSymbolAddress((void**)&gk, g_K);
    cudaGetSymbolAddress((void**)&gv, g_V);
    cudaGetSymbolAddress((void**)&gh, g_H);

    const int attn_smem = 3*64*65*(int)sizeof(float);   // 49920 B > 48K default
    cudaFuncSetAttribute(attn_kernel, cudaFuncAttributeMaxDynamicSharedMemorySize, attn_smem);

    rope_table_kernel<<<(S_LEN*(D_DIM/2) + 255)/256, 256>>>();

    dim3 ggrid(D_DIM/128, M_TOT/128);   // (8, 64)
    gemm128<2><<<ggrid, 256>>>(X, Wq, bq, gq);
    gemm128<2><<<ggrid, 256>>>(X, Wk, bk, gk);
    gemm128<1><<<ggrid, 256>>>(X, Wv, bv, gv);

    attn_kernel<<<dim3(S_LEN/64, NH, BATCH), 256, attn_smem>>>(gq, gk, gv, gh);

    gemm128<0><<<ggrid, 256>>>(gh, Wo, bo, out);
}

// round 2
// speedup vs baseline: 2.4364x; 2.4364x over previous
#include <cuda_runtime.h>
#include <math.h>

#define BATCH 4
#define S_LEN 2048
#define D_DIM 1024
#define NH    16
#define DH    64
#define M_TOT (BATCH*S_LEN)

// Scratch (device globals: allocation-free per harness rules)
__device__ float  g_Q[BATCH*NH*S_LEN*DH];   // [B,H,S,dh]
__device__ float  g_K[BATCH*NH*S_LEN*DH];
__device__ float  g_V[BATCH*NH*S_LEN*DH];
__device__ float  g_H[M_TOT*D_DIM];         // attention heads output [B,S,D]
__device__ float2 g_tab[S_LEN*(D_DIM/2)];   // RoPE (cos,sin)

// ---------------- helpers ----------------
__device__ __forceinline__ unsigned f2tf(float x){
    unsigned u; asm("cvt.rna.tf32.f32 %0, %1;" : "=r"(u) : "f"(x)); return u;
}
__device__ __forceinline__ void mma8(float* c, const unsigned* a, const unsigned* b){
    asm volatile("mma.sync.aligned.m16n8k8.row.col.f32.tf32.tf32.f32 "
        "{%0,%1,%2,%3}, {%4,%5,%6,%7}, {%8,%9}, {%0,%1,%2,%3};"
        : "+f"(c[0]), "+f"(c[1]), "+f"(c[2]), "+f"(c[3])
        : "r"(a[0]), "r"(a[1]), "r"(a[2]), "r"(a[3]), "r"(b[0]), "r"(b[1]));
}

// ---------------- RoPE table ----------------
__global__ void rope_table_kernel() {
    int idx = blockIdx.x*blockDim.x + threadIdx.x;
    if (idx >= S_LEN*(D_DIM/2)) return;
    int s = idx >> 9;
    int p = idx & 511;
    double inv = exp(-((double)(2*p) / (double)D_DIM) * log(10000.0));
    float ang = (float)s * (float)inv;
    float sn, cs;
    sincosf(ang, &sn, &cs);
    g_tab[idx] = make_float2(cs, sn);
}

// ---------------- tf32 GEMM: out = A[M,K] @ W[N,K]^T + bias ----------------
// MODE 0: row-major [M,N]; MODE 1: scatter [B,H,S,dh]; MODE 2: RoPE + scatter
template<int MODE>
__global__ __launch_bounds__(256) void gemm_tf32(
    const float* __restrict__ A, const float* __restrict__ W,
    const float* __restrict__ bias, float* __restrict__ out)
{
    __shared__ unsigned As[128][36];
    __shared__ unsigned Bs[128][36];
    int tid = threadIdx.x, lane = tid & 31, w = tid >> 5;
    int wm = (w >> 2) * 64, wn = (w & 3) * 32;
    int m0 = blockIdx.y * 128, n0 = blockIdx.x * 128;

    float acc[4][4][4];
    #pragma unroll
    for (int i=0;i<4;i++)
        #pragma unroll
        for (int j=0;j<4;j++)
            #pragma unroll
            for (int r=0;r<4;r++) acc[i][j][r] = 0.f;

    int lr = tid >> 1, lseg = (tid & 1) * 16;
    const float* Ap = A + (size_t)(m0 + lr) * D_DIM + lseg;
    const float* Wp = W + (size_t)(n0 + lr) * D_DIM + lseg;

    for (int k0 = 0; k0 < D_DIM; k0 += 32) {
        #pragma unroll
        for (int c = 0; c < 16; c += 4) {
            float4 va = *(const float4*)(Ap + k0 + c);
            uint4 ua = make_uint4(f2tf(va.x), f2tf(va.y), f2tf(va.z), f2tf(va.w));
            *(uint4*)&As[lr][lseg + c] = ua;
            float4 vb = *(const float4*)(Wp + k0 + c);
            uint4 ub = make_uint4(f2tf(vb.x), f2tf(vb.y), f2tf(vb.z), f2tf(vb.w));
            *(uint4*)&Bs[lr][lseg + c] = ub;
        }
        __syncthreads();
        #pragma unroll
        for (int ks = 0; ks < 4; ks++) {
            unsigned a[4][4];
            int kc = ks*8 + (lane & 3);
            #pragma unroll
            for (int fm = 0; fm < 4; fm++) {
                int r = wm + fm*16 + (lane >> 2);
                a[fm][0] = As[r][kc];
                a[fm][1] = As[r+8][kc];
                a[fm][2] = As[r][kc+4];
                a[fm][3] = As[r+8][kc+4];
            }
            #pragma unroll
            for (int fn = 0; fn < 4; fn++) {
                unsigned b[2];
                int n = wn + fn*8 + (lane >> 2);
                b[0] = Bs[n][kc];
                b[1] = Bs[n][kc+4];
                #pragma unroll
                for (int fm = 0; fm < 4; fm++) mma8(acc[fm][fn], a[fm], b);
            }
        }
        __syncthreads();
    }

    // Epilogue: bias (+ RoPE) + scatter. c0,c1 = cols (2j,2j+1) -> RoPE pair.
    #pragma unroll
    for (int fn = 0; fn < 4; fn++) {
        int colg = n0 + wn + fn*8 + (lane & 3)*2;
        float b0v = bias[colg], b1v = bias[colg+1];
        #pragma unroll
        for (int fm = 0; fm < 4; fm++) {
            int r0 = m0 + wm + fm*16 + (lane >> 2);
            #pragma unroll
            for (int half = 0; half < 2; half++) {
                int m = r0 + half*8;
                float v0 = acc[fm][fn][half*2+0] + b0v;
                float v1 = acc[fm][fn][half*2+1] + b1v;
                if (MODE == 2) {
                    int s = m & (S_LEN-1);
                    float2 cs = g_tab[s*512 + (colg >> 1)];
                    float e = v0*cs.x - v1*cs.y;
                    float d = v0*cs.y + v1*cs.x;
                    v0 = e; v1 = d;
                }
                if (MODE == 0) {
                    *(float2*)(out + (size_t)m*D_DIM + colg) = make_float2(v0, v1);
                } else {
                    int bb = m >> 11;
                    int s  = m & (S_LEN-1);
                    int hh = colg >> 6, d = colg & 63;
                    *(float2*)(out + ((size_t)(bb*NH + hh)*S_LEN + s)*DH + d) = make_float2(v0, v1);
                }
            }
        }
    }
}

// ---------------- tf32 flash attention ----------------
// Block: 128 q-rows of one (b,h). 8 warps, each warp owns 16 q-rows.
// smem: Ks[64][68] (tf32, [kpos][dh]), VT[64][68] ([dh][kpos]), Ps[128][68]
__global__ __launch_bounds__(256,1) void attn_tf32(
    const float* __restrict__ Q, const float* __restrict__ K,
    const float* __restrict__ V, float* __restrict__ O)
{
    extern __shared__ unsigned sm[];
    unsigned (*Ks)[68] = (unsigned(*)[68])sm;
    unsigned (*VT)[68] = (unsigned(*)[68])(sm + 64*68);
    unsigned (*Ps)[68] = (unsigned(*)[68])(sm + 2*64*68);

    int tid = threadIdx.x, lane = tid & 31, w = tid >> 5;
    int qb = blockIdx.x, h = blockIdx.y, b = blockIdx.z;

    const float* Qp = Q + ((size_t)(b*NH + h)*S_LEN + qb*128 + w*16)*DH;
    const float* Kp = K + (size_t)(b*NH + h)*S_LEN*DH;
    const float* Vp = V + (size_t)(b*NH + h)*S_LEN*DH;

    // Cache Q fragments in registers for the whole loop (scale folded in)
    unsigned qa[8][4];
    {
        int r = lane >> 2;
        #pragma unroll
        for (int ks = 0; ks < 8; ks++) {
            int c = ks*8 + (lane & 3);
            qa[ks][0] = f2tf(0.125f * Qp[(size_t)r*DH + c]);
            qa[ks][1] = f2tf(0.125f * Qp[(size_t)(r+8)*DH + c]);
            qa[ks][2] = f2tf(0.125f * Qp[(size_t)r*DH + c+4]);
            qa[ks][3] = f2tf(0.125f * Qp[(size_t)(r+8)*DH + c+4]);
        }
    }

    float m0r = -1e30f, m1r = -1e30f, l0r = 0.f, l1r = 0.f;
    float o[8][4];
    #pragma unroll
    for (int fn = 0; fn < 8; fn++)
        #pragma unroll
        for (int r = 0; r < 4; r++) o[fn][r] = 0.f;

    int lr = tid & 63;            // 32 distinct rows per warp -> conflict-free stores
    int lc = (tid >> 6) * 16;
    int pr0 = w*16 + (lane >> 2);

    for (int t = 0; t < S_LEN/64; t++) {
        __syncthreads();   // previous tile's PV reads done before overwrite
        #pragma unroll
        for (int c = 0; c < 16; c += 4) {
            float4 kv = *(const float4*)(Kp + (size_t)(t*64 + lr)*DH + lc + c);
            *(uint4*)&Ks[lr][lc + c] =
                make_uint4(f2tf(kv.x), f2tf(kv.y), f2tf(kv.z), f2tf(kv.w));
            float4 vv = *(const float4*)(Vp + (size_t)(t*64 + lr)*DH + lc + c);
            VT[lc+c+0][lr] = f2tf(vv.x);
            VT[lc+c+1][lr] = f2tf(vv.y);
            VT[lc+c+2][lr] = f2tf(vv.z);
            VT[lc+c+3][lr] = f2tf(vv.w);
        }
        __syncthreads();

        // S = (Q/8) K^T : warp tile 16q x 64k, 8 n-frags
        float s[8][4];
        #pragma unroll
        for (int fn = 0; fn < 8; fn++)
            #pragma unroll
            for (int r = 0; r < 4; r++) s[fn][r] = 0.f;

        #pragma unroll
        for (int ks = 0; ks < 8; ks++) {
            int kc = ks*8 + (lane & 3);
            #pragma unroll
            for (int fn = 0; fn < 8; fn++) {
                unsigned bb[2];
                int n = fn*8 + (lane >> 2);
                bb[0] = Ks[n][kc];
                bb[1] = Ks[n][kc+4];
                mma8(s[fn], qa[ks], bb);
            }
        }

        // Online softmax (rows l/4 and l/4+8; row lives in 4 lanes x 8 frags)
        float rm0 = -1e30f, rm1 = -1e30f;
        #pragma unroll
        for (int fn = 0; fn < 8; fn++) {
            rm0 = fmaxf(rm0, fmaxf(s[fn][0], s[fn][1]));
            rm1 = fmaxf(rm1, fmaxf(s[fn][2], s[fn][3]));
        }
        rm0 = fmaxf(rm0, __shfl_xor_sync(0xffffffffu, rm0, 1));
        rm0 = fmaxf(rm0, __shfl_xor_sync(0xffffffffu, rm0, 2));
        rm1 = fmaxf(rm1, __shfl_xor_sync(0xffffffffu, rm1, 1));
        rm1 = fmaxf(rm1, __shfl_xor_sync(0xffffffffu, rm1, 2));
        float mn0 = fmaxf(m0r, rm0), mn1 = fmaxf(m1r, rm1);
        float sum0 = 0.f, sum1 = 0.f;
        #pragma unroll
        for (int fn = 0; fn < 8; fn++) {
            s[fn][0] = __expf(s[fn][0] - mn0);
            s[fn][1] = __expf(s[fn][1] - mn0);
            s[fn][2] = __expf(s[fn][2] - mn1);
            s[fn][3] = __expf(s[fn][3] - mn1);
            sum0 += s[fn][0] + s[fn][1];
            sum1 += s[fn][2] + s[fn][3];
        }
        sum0 += __shfl_xor_sync(0xffffffffu, sum0, 1);
        sum0 += __shfl_xor_sync(0xffffffffu, sum0, 2);
        sum1 += __shfl_xor_sync(0xffffffffu, sum1, 1);
        sum1 += __shfl_xor_sync(0xffffffffu, sum1, 2);
        float alpha0 = __expf(m0r - mn0), alpha1 = __expf(m1r - mn1);
        l0r = l0r*alpha0 + sum0; m0r = mn0;
        l1r = l1r*alpha1 + sum1; m1r = mn1;
        #pragma unroll
        for (int fn = 0; fn < 8; fn++) {
            o[fn][0] *= alpha0; o[fn][1] *= alpha0;
            o[fn][2] *= alpha1; o[fn][3] *= alpha1;
        }

        // P -> smem (tf32); warp-private rows, so only __syncwarp needed
        #pragma unroll
        for (int fn = 0; fn < 8; fn++) {
            int pc = fn*8 + (lane & 3)*2;
            Ps[pr0][pc]     = f2tf(s[fn][0]);
            Ps[pr0][pc+1]   = f2tf(s[fn][1]);
            Ps[pr0+8][pc]   = f2tf(s[fn][2]);
            Ps[pr0+8][pc+1] = f2tf(s[fn][3]);
        }
        __syncwarp();

        // O += P @ V  (k-dim = 64 kpos)
        #pragma unroll
        for (int ks = 0; ks < 8; ks++) {
            int kc = ks*8 + (lane & 3);
            unsigned a[4];
            a[0] = Ps[pr0][kc];
            a[1] = Ps[pr0+8][kc];
            a[2] = Ps[pr0][kc+4];
            a[3] = Ps[pr0+8][kc+4];
            #pragma unroll
            for (int fn = 0; fn < 8; fn++) {
                unsigned bb[2];
                int n = fn*8 + (lane >> 2);
                bb[0] = VT[n][kc];
                bb[1] = VT[n][kc+4];
                mma8(o[fn], a, bb);
            }
        }
    }

    // Writeback to [B,S,D]
    float inv0 = 1.f / l0r, inv1 = 1.f / l1r;
    int sg = qb*128 + w*16 + (lane >> 2);
    float* Op0 = O + ((size_t)b*S_LEN + sg)*D_DIM + h*DH;
    float* Op1 = Op0 + (size_t)8*D_DIM;
    #pragma unroll
    for (int fn = 0; fn < 8; fn++) {
        int col = fn*8 + (lane & 3)*2;
        *(float2*)(Op0 + col) = make_float2(o[fn][0]*inv0, o[fn][1]*inv0);
        *(float2*)(Op1 + col) = make_float2(o[fn][2]*inv1, o[fn][3]*inv1);
    }
}

extern "C" void kernel_launch(void* const* d_in, const int* in_sizes, int n_in,
                              void* d_out, int out_size)
{
    const float* X  = (const float*)d_in[0];
    const float* Wq = (const float*)d_in[1];
    const float* bq = (const float*)d_in[2];
    const float* Wk = (const float*)d_in[3];
    const float* bk = (const float*)d_in[4];
    const float* Wv = (const float*)d_in[5];
    const float* bv = (const float*)d_in[6];
    const float* Wo = (const float*)d_in[7];
    const float* bo = (const float*)d_in[8];
    float* out = (float*)d_out;

    float *gq, *gk, *gv, *gh;
    cudaGetSymbolAddress((void**)&gq, g_Q);
    cudaGetSymbolAddress((void**)&gk, g_K);
    cudaGetSymbolAddress((void**)&gv, g_V);
    cudaGetSymbolAddress((void**)&gh, g_H);

    const int attn_smem = (2*64*68 + 128*68) * (int)sizeof(unsigned);  // 69632 B
    cudaFuncSetAttribute(attn_tf32, cudaFuncAttributeMaxDynamicSharedMemorySize, attn_smem);

    rope_table_kernel<<<(S_LEN*(D_DIM/2) + 255)/256, 256>>>();

    dim3 ggrid(D_DIM/128, M_TOT/128);   // (8, 64)
    gemm_tf32<2><<<ggrid, 256>>>(X, Wq, bq, gq);
    gemm_tf32<2><<<ggrid, 256>>>(X, Wk, bk, gk);
    gemm_tf32<1><<<ggrid, 256>>>(X, Wv, bv, gv);

    attn_tf32<<<dim3(S_LEN/128, NH, BATCH), 256, attn_smem>>>(gq, gk, gv, gh);

    gemm_tf32<0><<<ggrid, 256>>>(gh, Wo, bo, out);
}

// round 5
// speedup vs baseline: 3.3291x; 1.3664x over previous
#include <cuda_runtime.h>
#include <math.h>
#include <stdint.h>

#define BATCH 4
#define S_LEN 2048
#define D_DIM 1024
#define NH    16
#define DH    64
#define M_TOT (BATCH*S_LEN)

__device__ float  g_Q[BATCH*NH*S_LEN*DH];
__device__ float  g_K[BATCH*NH*S_LEN*DH];
__device__ float  g_V[BATCH*NH*S_LEN*DH];
__device__ float  g_H[M_TOT*D_DIM];
__device__ float2 g_tab[S_LEN*(D_DIM/2)];

__device__ __forceinline__ unsigned f2tf(float x){
    unsigned u; asm("cvt.rna.tf32.f32 %0, %1;" : "=r"(u) : "f"(x)); return u;
}
__device__ __forceinline__ void mma8(float* c, const unsigned* a, const unsigned* b){
    asm volatile("mma.sync.aligned.m16n8k8.row.col.f32.tf32.tf32.f32 "
        "{%0,%1,%2,%3}, {%4,%5,%6,%7}, {%8,%9}, {%0,%1,%2,%3};"
        : "+f"(c[0]), "+f"(c[1]), "+f"(c[2]), "+f"(c[3])
        : "r"(a[0]), "r"(a[1]), "r"(a[2]), "r"(a[3]), "r"(b[0]), "r"(b[1]));
}

__global__ void rope_table_kernel() {
    int idx = blockIdx.x*blockDim.x + threadIdx.x;
    if (idx >= S_LEN*512) return;
    int s = idx >> 9, p = idx & 511;
    double inv = exp(-((double)(2*p) / (double)D_DIM) * log(10000.0));
    float ang = (float)s * (float)inv;
    float sn, cs; sincosf(ang, &sn, &cs);
    g_tab[idx] = make_float2(cs, sn);
}

// ============ GEMM: out = A[M,1024] @ W[N,1024]^T + bias. 4 warps, warp 64x64 ============
// smem layout: S[c][ (col + 8*(c>>2)) & 127 ], stride 136 words.
template<int MODE>
__global__ __launch_bounds__(128,2) void gemm_v3(
    const float* __restrict__ A, const float* __restrict__ W,
    const float* __restrict__ bias, float* __restrict__ out)
{
    __shared__ unsigned As[2][16*136], Bs[2][16*136];
    int tid = threadIdx.x, lane = tid & 31, w = tid >> 5;
    int rr = lane >> 2, cb = lane & 3;
    int wm = (w >> 1) * 64, wn = (w & 1) * 64;
    int m0 = blockIdx.y * 128, n0 = blockIdx.x * 128;

    float acc[4][8][4];
    #pragma unroll
    for (int i=0;i<4;i++)
        #pragma unroll
        for (int j=0;j<8;j++)
            #pragma unroll
            for (int e=0;e<4;e++) acc[i][j][e] = 0.f;

    float4 av[4], bv[4];
    #pragma unroll
    for (int l=0;l<4;l++){ int slot = tid + l*128; int m = slot>>2, kq = slot&3;
        av[l] = *(const float4*)(A + (size_t)(m0+m)*D_DIM + kq*4);
        bv[l] = *(const float4*)(W + (size_t)(n0+m)*D_DIM + kq*4); }
    #pragma unroll
    for (int l=0;l<4;l++){ int slot = tid + l*128; int m = slot>>2, kq = slot&3;
        const float* a4 = (const float*)&av[l];
        const float* b4 = (const float*)&bv[l];
        #pragma unroll
        for (int j=0;j<4;j++){
            As[0][(kq*4+j)*136 + ((m + 8*kq) & 127)] = f2tf(a4[j]);
            Bs[0][(kq*4+j)*136 + ((m + 8*kq) & 127)] = f2tf(b4[j]); } }
    __syncthreads();

    for (int it = 0; it < 64; it++){
        int cur = it & 1;
        if (it + 1 < 64){
            int k0 = (it+1)*16;
            #pragma unroll
            for (int l=0;l<4;l++){ int slot = tid + l*128; int m = slot>>2, kq = slot&3;
                av[l] = *(const float4*)(A + (size_t)(m0+m)*D_DIM + k0 + kq*4);
                bv[l] = *(const float4*)(W + (size_t)(n0+m)*D_DIM + k0 + kq*4); }
        }
        #pragma unroll
        for (int ks = 0; ks < 2; ks++){
            int c1 = ks*8 + cb, off = 16*ks;
            unsigned a[4][4], b[8][2];
            #pragma unroll
            for (int fm = 0; fm < 4; fm++){
                int r = wm + rr + fm*16;
                a[fm][0] = As[cur][c1*136 + ((r + off) & 127)];
                a[fm][1] = As[cur][c1*136 + ((r + 8 + off) & 127)];
                a[fm][2] = As[cur][(c1+4)*136 + ((r + off + 8) & 127)];
                a[fm][3] = As[cur][(c1+4)*136 + ((r + 8 + off + 8) & 127)];
            }
            #pragma unroll
            for (int fn = 0; fn < 8; fn++){
                int n = wn + rr + fn*8;
                b[fn][0] = Bs[cur][c1*136 + ((n + off) & 127)];
                b[fn][1] = Bs[cur][(c1+4)*136 + ((n + off + 8) & 127)];
            }
            #pragma unroll
            for (int fm = 0; fm < 4; fm++)
                #pragma unroll
                for (int fn = 0; fn < 8; fn++)
                    mma8(acc[fm][fn], a[fm], b[fn]);
        }
        if (it + 1 < 64){
            int nxt = cur ^ 1;
            #pragma unroll
            for (int l=0;l<4;l++){ int slot = tid + l*128; int m = slot>>2, kq = slot&3;
                const float* a4 = (const float*)&av[l];
                const float* b4 = (const float*)&bv[l];
                #pragma unroll
                for (int j=0;j<4;j++){
                    As[nxt][(kq*4+j)*136 + ((m + 8*kq) & 127)] = f2tf(a4[j]);
                    Bs[nxt][(kq*4+j)*136 + ((m + 8*kq) & 127)] = f2tf(b4[j]); } }
            __syncthreads();
        }
    }

    #pragma unroll
    for (int fn = 0; fn < 8; fn++){
        int colg = n0 + wn + fn*8 + cb*2;
        float b0v = bias[colg], b1v = bias[colg+1];
        #pragma unroll
        for (int fm = 0; fm < 4; fm++){
            #pragma unroll
            for (int half = 0; half < 2; half++){
                int m = m0 + wm + fm*16 + rr + half*8;
                float v0 = acc[fm][fn][half*2+0] + b0v;
                float v1 = acc[fm][fn][half*2+1] + b1v;
                int srow = m & (S_LEN-1);
                if (MODE == 2){
                    float2 cs = g_tab[srow*512 + (colg >> 1)];
                    float e = v0*cs.x - v1*cs.y;
                    float d = v0*cs.y + v1*cs.x;
                    v0 = e; v1 = d;
                }
                if (MODE == 0){
                    *(float2*)(out + (size_t)m*D_DIM + colg) = make_float2(v0, v1);
                } else {
                    int bb = m >> 11, hh = colg >> 6, dd = colg & 63;
                    *(float2*)(out + ((size_t)(bb*NH+hh)*S_LEN + srow)*DH + dd) = make_float2(v0, v1);
                }
            }
        }
    }
}

// ============ Flash attention: 8 warps x 32q x 64k, K/V double-buffered ============
// K: Ks[dh][ (kpos + 2*(dh>>2)) & 63 ], V: Vs[kpos][ (dh + 2*(kpos>>2)) & 63 ],
// P: Pw[rl][ (kc + 4*(rl>>2)) & 63 ], all stride 72 words.
__global__ __launch_bounds__(256,1) void attn_v3(
    const float* __restrict__ Q, const float* __restrict__ K,
    const float* __restrict__ V, float* __restrict__ O)
{
    extern __shared__ unsigned sm[];
    int tid = threadIdx.x, lane = tid & 31, w = tid >> 5;
    int rr = lane >> 2, cb = lane & 3;
    int qb = blockIdx.x, hd = blockIdx.y, b = blockIdx.z;

    const float* Qp = Q + ((size_t)(b*NH + hd)*S_LEN + qb*256 + w*32)*DH;
    const float* Kp = K + (size_t)(b*NH + hd)*S_LEN*DH;
    const float* Vp = V + (size_t)(b*NH + hd)*S_LEN*DH;
    unsigned* Pw = sm + 18432 + (w*32)*72;

    unsigned q[2][8][4];
    #pragma unroll
    for (int fm = 0; fm < 2; fm++){
        int r0 = fm*16 + rr;
        #pragma unroll
        for (int ks = 0; ks < 8; ks++){
            int c = ks*8 + cb;
            q[fm][ks][0] = f2tf(0.125f * Qp[(size_t)r0*DH + c]);
            q[fm][ks][1] = f2tf(0.125f * Qp[(size_t)(r0+8)*DH + c]);
            q[fm][ks][2] = f2tf(0.125f * Qp[(size_t)r0*DH + c+4]);
            q[fm][ks][3] = f2tf(0.125f * Qp[(size_t)(r0+8)*DH + c+4]);
        }
    }

    float m_[2][2], l_[2][2], o[2][8][4];
    #pragma unroll
    for (int fm=0;fm<2;fm++)
        #pragma unroll
        for (int hh=0;hh<2;hh++){ m_[fm][hh] = -1e30f; l_[fm][hh] = 0.f; }
    #pragma unroll
    for (int fm=0;fm<2;fm++)
        #pragma unroll
        for (int fn=0;fn<8;fn++)
            #pragma unroll
            for (int e=0;e<4;e++) o[fm][fn][e] = 0.f;

    float4 kst[4], vst[4];
    #pragma unroll
    for (int l=0;l<4;l++){ int slot = tid + l*256; int kp = slot>>4, cq = slot&15;
        kst[l] = *(const float4*)(Kp + (size_t)kp*DH + cq*4);
        vst[l] = *(const float4*)(Vp + (size_t)kp*DH + cq*4); }
    #pragma unroll
    for (int l=0;l<4;l++){ int slot = tid + l*256; int kp = slot>>4, cq = slot&15;
        const float* kv = (const float*)&kst[l];
        const float* vv = (const float*)&vst[l];
        #pragma unroll
        for (int j=0;j<4;j++){
            sm[(cq*4+j)*72 + ((kp + 2*cq) & 63)] = f2tf(kv[j]);
            sm[9216 + kp*72 + ((cq*4+j + 2*(kp>>2)) & 63)] = f2tf(vv[j]); } }
    __syncthreads();

    for (int t = 0; t < 32; t++){
        int cur = t & 1;
        const unsigned* Kc = sm + cur*4608;
        const unsigned* Vc = sm + 9216 + cur*4608;
        if (t + 1 < 32){
            const float* Kn = Kp + (size_t)(t+1)*64*DH;
            const float* Vn = Vp + (size_t)(t+1)*64*DH;
            #pragma unroll
            for (int l=0;l<4;l++){ int slot = tid + l*256; int kp = slot>>4, cq = slot&15;
                kst[l] = *(const float4*)(Kn + (size_t)kp*DH + cq*4);
                vst[l] = *(const float4*)(Vn + (size_t)kp*DH + cq*4); }
        }

        float s[2][8][4];
        #pragma unroll
        for (int fm=0;fm<2;fm++)
            #pragma unroll
            for (int fn=0;fn<8;fn++)
                #pragma unroll
                for (int e=0;e<4;e++) s[fm][fn][e] = 0.f;

        #pragma unroll
        for (int ks = 0; ks < 8; ks++){
            int c1 = ks*8 + cb;
            #pragma unroll
            for (int fn = 0; fn < 8; fn++){
                int n = fn*8 + rr;
                unsigned bb[2];
                bb[0] = Kc[c1*72 + ((n + 4*ks) & 63)];
                bb[1] = Kc[(c1+4)*72 + ((n + 4*ks + 2) & 63)];
                mma8(s[0][fn], q[0][ks], bb);
                mma8(s[1][fn], q[1][ks], bb);
            }
        }

        #pragma unroll
        for (int fm = 0; fm < 2; fm++)
            #pragma unroll
            for (int hh = 0; hh < 2; hh++){
                float rm = -1e30f;
                #pragma unroll
                for (int fn = 0; fn < 8; fn++)
                    rm = fmaxf(rm, fmaxf(s[fm][fn][hh*2], s[fm][fn][hh*2+1]));
                rm = fmaxf(rm, __shfl_xor_sync(0xffffffffu, rm, 1));
                rm = fmaxf(rm, __shfl_xor_sync(0xffffffffu, rm, 2));
                float mn = fmaxf(m_[fm][hh], rm);
                float sum = 0.f;
                #pragma unroll
                for (int fn = 0; fn < 8; fn++){
                    s[fm][fn][hh*2]   = __expf(s[fm][fn][hh*2]   - mn);
                    s[fm][fn][hh*2+1] = __expf(s[fm][fn][hh*2+1] - mn);
                    sum += s[fm][fn][hh*2] + s[fm][fn][hh*2+1];
                }
                sum += __shfl_xor_sync(0xffffffffu, sum, 1);
                sum += __shfl_xor_sync(0xffffffffu, sum, 2);
                float alpha = __expf(m_[fm][hh] - mn);
                l_[fm][hh] = l_[fm][hh]*alpha + sum;
                m_[fm][hh] = mn;
                #pragma unroll
                for (int fn = 0; fn < 8; fn++){
                    o[fm][fn][hh*2]   *= alpha;
                    o[fm][fn][hh*2+1] *= alpha;
                }
            }

        #pragma unroll
        for (int fm = 0; fm < 2; fm++)
            #pragma unroll
            for (int hh = 0; hh < 2; hh++){
                int rl = fm*16 + rr + 8*hh;
                int ro = 4*(rl>>2);
                #pragma unroll
                for (int fn = 0; fn < 8; fn++){
                    int pc = fn*8 + cb*2;
                    *(uint2*)&Pw[rl*72 + ((pc + ro) & 63)] =
                        make_uint2(f2tf(s[fm][fn][hh*2]), f2tf(s[fm][fn][hh*2+1]));
                }
            }
        __syncwarp();

        #pragma unroll
        for (int ks = 0; ks < 8; ks++){
            int kc = ks*8 + cb;
            unsigned a[2][4];
            #pragma unroll
            for (int fm = 0; fm < 2; fm++){
                int r0 = fm*16 + rr, r1 = r0 + 8;
                a[fm][0] = Pw[r0*72 + ((kc + 4*(r0>>2)) & 63)];
                a[fm][1] = Pw[r1*72 + ((kc + 4*(r1>>2)) & 63)];
                a[fm][2] = Pw[r0*72 + ((kc + 4 + 4*(r0>>2)) & 63)];
                a[fm][3] = Pw[r1*72 + ((kc + 4 + 4*(r1>>2)) & 63)];
            }
            #pragma unroll
            for (int fn = 0; fn < 8; fn++){
                int n = fn*8 + rr;
                unsigned bb[2];
                bb[0] = Vc[kc*72 + ((n + 4*ks) & 63)];
                bb[1] = Vc[(kc+4)*72 + ((n + 4*ks + 2) & 63)];
                mma8(o[0][fn], a[0], bb);
                mma8(o[1][fn], a[1], bb);
            }
        }

        __syncthreads();
        if (t + 1 < 32){
            unsigned* Kw = sm + (cur^1)*4608;
            unsigned* Vw = sm + 9216 + (cur^1)*4608;
            #pragma unroll
            for (int l=0;l<4;l++){ int slot = tid + l*256; int kp = slot>>4, cq = slot&15;
                const float* kv = (const float*)&kst[l];
                const float* vv = (const float*)&vst[l];
                #pragma unroll
                for (int j=0;j<4;j++){
                    Kw[(cq*4+j)*72 + ((kp + 2*cq) & 63)] = f2tf(kv[j]);
                    Vw[kp*72 + ((cq*4+j + 2*(kp>>2)) & 63)] = f2tf(vv[j]); } }
            __syncthreads();
        }
    }

    #pragma unroll
    for (int fm = 0; fm < 2; fm++)
        #pragma unroll
        for (int hh = 0; hh < 2; hh++){
            float inv = 1.f / l_[fm][hh];
            int sg = qb*256 + w*32 + fm*16 + rr + 8*hh;
            float* Op = O + ((size_t)b*S_LEN + sg)*D_DIM + hd*DH;
            #pragma unroll
            for (int fn = 0; fn < 8; fn++){
                int col = fn*8 + cb*2;
                *(float2*)(Op + col) =
                    make_float2(o[fm][fn][hh*2]*inv, o[fm][fn][hh*2+1]*inv);
            }
        }
}

extern "C" void kernel_launch(void* const* d_in, const int* in_sizes, int n_in,
                              void* d_out, int out_size)
{
    const float* X  = (const float*)d_in[0];
    const float* Wq = (const float*)d_in[1];
    const float* bq = (const float*)d_in[2];
    const float* Wk = (const float*)d_in[3];
    const float* bk = (const float*)d_in[4];
    const float* Wv = (const float*)d_in[5];
    const float* bv = (const float*)d_in[6];
    const float* Wo = (const float*)d_in[7];
    const float* bo = (const float*)d_in[8];
    float* out = (float*)d_out;

    float *gq, *gk, *gv, *gh;
    cudaGetSymbolAddress((void**)&gq, g_Q);
    cudaGetSymbolAddress((void**)&gk, g_K);
    cudaGetSymbolAddress((void**)&gv, g_V);
    cudaGetSymbolAddress((void**)&gh, g_H);

    const int attn_smem = (4*4608 + 256*72) * (int)sizeof(unsigned);  // 147456 B
    cudaFuncSetAttribute(attn_v3, cudaFuncAttributeMaxDynamicSharedMemorySize, attn_smem);

    rope_table_kernel<<<(S_LEN*512 + 255)/256, 256>>>();

    dim3 ggrid(D_DIM/128, M_TOT/128);   // (8, 64)
    gemm_v3<2><<<ggrid, 128>>>(X, Wq, bq, gq);
    gemm_v3<2><<<ggrid, 128>>>(X, Wk, bk, gk);
    gemm_v3<1><<<ggrid, 128>>>(X, Wv, bv, gv);

    attn_v3<<<dim3(S_LEN/256, NH, BATCH), 256, attn_smem>>>(gq, gk, gv, gh);

    gemm_v3<0><<<ggrid, 128>>>(gh, Wo, bo, out);
}